// round 13
// baseline (speedup 1.0000x reference)
#include <cuda_runtime.h>
#include <cuda_bf16.h>

#define O_    4
#define N_    3072
#define NPAIR (N_ / 2)
#define KNN   10
#define TOLC  0.01f
#define FMAXV 3.402823466e+38f
#define BTHR  128            // threads per knn block (1 query/thread)
#define CAP   112            // per-thread insert buffer (mean ~57, ~7 sigma)
#define FULLM 0xFFFFFFFFu

// ---------------- device scratch (no allocations allowed) ----------------
__device__ float4     g_pip4[O_ * N_];     // (x, y, z, |p|^2) — queries / finalize
__device__ float4     g_nrm4[O_ * N_];     // raw normal
__device__ ulonglong2 g_pkA[O_][NPAIR];    // pair-packed {X=(x0,x1), Y=(y0,y1)}
__device__ ulonglong2 g_pkB[O_][NPAIR];    // pair-packed {Z=(z0,z1), W=(w0,w1)}
__device__ float      g_scr[O_][3][N_];    // signed nearest distance per (b, oi, n)

// ---------------- packed f32x2 helpers (IEEE per-lane, bit-identical to scalar) ----------------
__device__ __forceinline__ unsigned long long pk2(float lo, float hi) {
    unsigned long long r;
    asm("mov.b64 %0, {%1, %2};" : "=l"(r) : "f"(lo), "f"(hi));
    return r;
}
__device__ __forceinline__ unsigned long long fma2(unsigned long long a,
                                                   unsigned long long b,
                                                   unsigned long long c) {
    unsigned long long d;
    asm("fma.rn.f32x2 %0, %1, %2, %3;" : "=l"(d) : "l"(a), "l"(b), "l"(c));
    return d;
}
__device__ __forceinline__ void upk2(unsigned long long v, float& lo, float& hi) {
    asm("mov.b64 {%0, %1}, %2;" : "=f"(lo), "=f"(hi) : "l"(v));
}

// ---------------- kernel 1: prep + transform fused, writes packed layout ----------------
__global__ void transform_kernel(const float* __restrict__ points,
                                 const float* __restrict__ T_obj,
                                 const float* __restrict__ T_plane) {
    int i = blockIdx.x * blockDim.x + threadIdx.x;
    if (i >= O_ * N_) return;
    int o = i / N_;
    int nn = i - o * N_;

    float Rp[9], tp[3];
    #pragma unroll
    for (int r = 0; r < 3; r++) {
        #pragma unroll
        for (int c = 0; c < 3; c++) Rp[r * 3 + c] = __ldg(&T_plane[r * 4 + c]);
        tp[r] = __ldg(&T_plane[r * 4 + 3]);
    }
    const float* To = T_obj + o * 16;
    // inv(T_plane) rigid: [Rp^T | -Rp^T tp]
    float R[3][3], tr[3];
    #pragma unroll
    for (int r = 0; r < 3; r++) {
        R[r][0] = Rp[0 + r] * To[0] + Rp[3 + r] * To[4] + Rp[6 + r] * To[8];
        R[r][1] = Rp[0 + r] * To[1] + Rp[3 + r] * To[5] + Rp[6 + r] * To[9];
        R[r][2] = Rp[0 + r] * To[2] + Rp[3 + r] * To[6] + Rp[6 + r] * To[10];
        tr[r]   = Rp[0 + r] * (To[3] - tp[0]) + Rp[3 + r] * (To[7] - tp[1])
                + Rp[6 + r] * (To[11] - tp[2]);
    }

    const float* p = points + (size_t)i * 6;
    float x = p[0], y = p[1], z = p[2];
    float px = fmaf(R[0][0], x, fmaf(R[0][1], y, fmaf(R[0][2], z, tr[0])));
    float py = fmaf(R[1][0], x, fmaf(R[1][1], y, fmaf(R[1][2], z, tr[1])));
    float pz = fmaf(R[2][0], x, fmaf(R[2][1], y, fmaf(R[2][2], z, tr[2])));
    float rr = px * px + py * py + pz * pz;
    g_pip4[i] = make_float4(px, py, pz, rr);
    g_nrm4[i] = make_float4(p[3], p[4], p[5], 0.f);

    // pair-packed SoA: A[p] = {x0,x1,y0,y1}, B[p] = {z0,z1,w0,w1}
    int pr = nn >> 1, l = nn & 1;
    float* A = (float*)&g_pkA[o][0];
    float* B = (float*)&g_pkB[o][0];
    A[pr * 4 + l]     = px;
    A[pr * 4 + 2 + l] = py;
    B[pr * 4 + l]     = pz;
    B[pr * 4 + 2 + l] = rr;
}

// scalar distance of candidate id from packed smem floats (rare paths)
__device__ __forceinline__ float cand_d(const float* fA, const float* fB, int id,
                                        float m2x, float m2y, float m2z) {
    int p = id >> 1, l = id & 1;
    float x = fA[p * 4 + l],  y = fA[p * 4 + 2 + l];
    float z = fB[p * 4 + l],  w = fB[p * 4 + 2 + l];
    return fmaf(x, m2x, fmaf(y, m2y, fmaf(z, m2z, w)));
}

// ---------------- kernel 2: exact top-10 — packed-f32x2 scan + bitmask replay ----------------
// smem: [0,24K) A pairs ; [24K,48K) B pairs ; [48K,+28K) insert-id buffer u16
__global__ void __launch_bounds__(BTHR) knn_kernel() {
    extern __shared__ char smem_raw[];
    ulonglong2* shA = (ulonglong2*)smem_raw;            // [NPAIR]
    ulonglong2* shB = shA + NPAIR;                      // [NPAIR]
    const float* fA = (const float*)shA;
    const float* fB = (const float*)shB;
    unsigned short* buf = (unsigned short*)(shB + NPAIR);  // buf[slot*BTHR + tid]

    int pair = blockIdx.y;
    int b  = pair / 3;
    int oi = pair - b * 3;
    int o  = oi + (oi >= b ? 1 : 0);
    int tid = threadIdx.x;
    int n  = blockIdx.x * BTHR + tid;

    {
        const ulonglong2* gA = &g_pkA[o][0];
        const ulonglong2* gB = &g_pkB[o][0];
        for (int i = tid; i < NPAIR; i += BTHR) { shA[i] = gA[i]; shB[i] = gB[i]; }
    }
    __syncthreads();

    float4 q = g_pip4[b * N_ + n];
    float m2x = -2.f * q.x, m2y = -2.f * q.y, m2z = -2.f * q.z;
    unsigned long long M2X = pk2(m2x, m2x);
    unsigned long long M2Y = pk2(m2y, m2y);
    unsigned long long M2Z = pk2(m2z, m2z);

    float a[KNN];
    #pragma unroll
    for (int s = 0; s < KNN; s++) a[s] = FMAXV;
    float thresh = FMAXV;
    int cnt = 0;

    #define INSERT(idv, dv)                                     \
        do { int _slot = cnt < CAP - 1 ? cnt : CAP - 1;         \
             buf[_slot * BTHR + tid] = (unsigned short)(idv);   \
             cnt++;                                             \
             float _t = (dv);                                   \
             _Pragma("unroll")                                  \
             for (int _s = 0; _s < KNN; _s++) {                 \
                 float _lo = fminf(a[_s], _t);                  \
                 _t = fmaxf(a[_s], _t);                         \
                 a[_s] = _lo;                                   \
             }                                                  \
             thresh = a[KNN - 1]; } while (0)

    // ---- scan: 16 pairs (32 candidates) per chunk; packed math; replay set bits ----
    #pragma unroll 1
    for (int p0 = 0; p0 < NPAIR; p0 += 16) {
        unsigned mask = 0u;
        #pragma unroll
        for (int u = 0; u < 16; u++) {
            ulonglong2 va = shA[p0 + u];         // X=(x0,x1), Y=(y0,y1)
            ulonglong2 vb = shB[p0 + u];         // Z=(z0,z1), W=(w0,w1)
            unsigned long long D =
                fma2(va.x, M2X, fma2(va.y, M2Y, fma2(vb.x, M2Z, vb.y)));
            float d0, d1; upk2(D, d0, d1);
            mask |= (fminf(d0, d1) < thresh) ? (1u << u) : 0u;
        }
        #pragma unroll 1
        while (__any_sync(FULLM, mask != 0u)) {
            if (mask) {
                int bit = __ffs(mask) - 1;
                mask &= mask - 1u;
                int p = p0 + bit;
                // recheck both candidates of the pair against refined threshold,
                // ascending id order (matches top_k tie behavior)
                float d0 = cand_d(fA, fB, 2 * p,     m2x, m2y, m2z);
                if (d0 < thresh) INSERT(2 * p, d0);
                float d1 = cand_d(fA, fB, 2 * p + 1, m2x, m2y, m2z);
                if (d1 < thresh) INSERT(2 * p + 1, d1);
            }
        }
    }
    // a[0..9] is the EXACT top-10: any candidate below the final threshold had
    // min(pair) < scan-time threshold (monotone decreasing) -> bit set -> replayed.

    // ---- final id selection: first 10 buffered ids (ascending j) with d <= a[9] ----
    unsigned ids[KNN];
    int w = 0;
    if (cnt < CAP) {
        #pragma unroll 1
        for (int t = 0; t < cnt && w < KNN; t++) {
            unsigned id = buf[t * BTHR + tid];
            float d = cand_d(fA, fB, id, m2x, m2y, m2z);
            if (d <= thresh) ids[w++] = id;
        }
    } else {
        // overflow fallback (P ~ 1e-9/thread): exact rescan in ascending j
        #pragma unroll 1
        for (int j = 0; j < N_ && w < KNN; j++) {
            float d = cand_d(fA, fB, j, m2x, m2y, m2z);
            if (d <= thresh) ids[w++] = (unsigned)j;
        }
    }
    while (w < KNN) ids[w++] = ids[0];   // safety (unreachable)

    // ---- exact d0 + inside votes ----
    float D0 = q.w + a[0];
    float d0 = sqrtf(fmaxf(D0, 0.f));

    int votes = 0;
    const float4* nrm = g_nrm4 + o * N_;
    #pragma unroll
    for (int s = 0; s < KNN; s++) {
        unsigned id = ids[s];
        int p = id >> 1, l = id & 1;
        float cx = fA[p * 4 + l], cy = fA[p * 4 + 2 + l], cz = fB[p * 4 + l];
        float4 nm = __ldg(&nrm[id]);
        float dt = (cx - q.x) * nm.x + (cy - q.y) * nm.y + (cz - q.z) * nm.z;
        votes += (dt > 0.f) ? 1 : 0;
    }
    float sd = (votes > 8) ? -d0 : d0;   // sum(insides) > 0.8*k -> >= 9
    g_scr[b][oi][n] = sd;

    #undef INSERT
}

// ---------------- kernel 3: min over other objects + plane, write out ----------------
__global__ void finalize_kernel(float* __restrict__ out, int out_size) {
    int i = blockIdx.x * blockDim.x + threadIdx.x;
    if (i >= O_ * N_) return;
    int b = i / N_;
    int n = i % N_;
    float sd = g_pip4[i].z;                 // plane signed distance = pip.z
    sd = fminf(sd, g_scr[b][0][n]);
    sd = fminf(sd, g_scr[b][1][n]);
    sd = fminf(sd, g_scr[b][2][n]);
    out[i] = sd;
    if (out_size >= 2 * O_ * N_)
        out[O_ * N_ + i] = (sd < -TOLC) ? 1.0f : 0.0f;
}

// ---------------- launch ----------------
extern "C" void kernel_launch(void* const* d_in, const int* in_sizes, int n_in,
                              void* d_out, int out_size) {
    const float* points  = nullptr;
    const float* T_obj   = nullptr;
    const float* T_plane = nullptr;
    for (int i = 0; i < n_in; i++) {
        if (in_sizes[i] == O_ * N_ * 6) points  = (const float*)d_in[i];
        else if (in_sizes[i] == 64)     T_obj   = (const float*)d_in[i];
        else if (in_sizes[i] == 16)     T_plane = (const float*)d_in[i];
    }

    transform_kernel<<<(O_ * N_ + 255) / 256, 256>>>(points, T_obj, T_plane);

    int smem = N_ * (int)sizeof(float4) + CAP * BTHR * (int)sizeof(unsigned short);
    (void)cudaFuncSetAttribute(knn_kernel,
                               cudaFuncAttributeMaxDynamicSharedMemorySize, smem);
    knn_kernel<<<dim3(N_ / BTHR, O_ * 3), BTHR, smem>>>();

    finalize_kernel<<<(O_ * N_ + 255) / 256, 256>>>((float*)d_out, out_size);
}